// round 5
// baseline (speedup 1.0000x reference)
#include <cuda_runtime.h>

// Problem constants
#define BB 16
#define KK 8
#define CC 64
#define LL 2048
#define CL (CC*LL)                 // 131072 elements per batch
#define CL4 (CL/4)                 // 32768 float4 per batch
#define TPB 256
#define BLK_PER_BATCH (CL4/TPB)    // 128 blocks per batch
#define NBLK (BB*BLK_PER_BATCH)    // 2048 blocks total

// Scratch for deterministic sldj reduction (allocations are forbidden).
__device__ float        g_partials[NBLK];
__device__ unsigned int g_counter = 0;

__device__ __forceinline__ float frcp(float x) {
    float r; asm("rcp.approx.f32 %0, %1;" : "=f"(r) : "f"(x)); return r;
}

// min-blocks 6 => <=40 regs/thread => 6 CTAs/SM => 48/64 warps resident.
__global__ __launch_bounds__(TPB, 6) void coupling_fused(
    const float4* __restrict__ x4, const float4* __restrict__ a4,
    const float4* __restrict__ b4, const float4* __restrict__ pi4,
    const float4* __restrict__ mu4, const float4* __restrict__ s4,
    const float*  __restrict__ sldj_in,
    float4* __restrict__ out4, float* __restrict__ out_sldj)
{
    const int blk = blockIdx.x;
    const int bat = blk / BLK_PER_BATCH;
    const int j4  = (blk - bat * BLK_PER_BATCH) * TPB + threadIdx.x; // float4 idx in batch
    const int xi  = bat * CL4 + j4;              // float4 idx into [B,C,L]
    const int kb  = bat * KK * CL4 + j4;         // float4 idx into [B,K,C,L] (k=0)

    // Independent loads up front: join the first MLP batch.
    float4 xv = x4[xi];
    float4 av = a4[xi];
    float4 bv = b4[xi];
    const float x_[4] = {xv.x, xv.y, xv.z, xv.w};

    // Single fused pass. No softmax max-subtraction: pi ~ N(0,1), exp(pi) is
    // always finite in fp32 (overflow would need pi > 88).
    //   w_k  = exp(pi_k)               (unnormalized softmax weight)
    //   z_k  = (x - mu_k) * exp(-s_k)
    //   sig  = 1/(1+exp(-z)),  1-sig = exp(-z)*sig
    //   W   = sum w
    //   S1  = sum w * sig                       -> u = S1/W
    //   S2  = sum w * e^-s * sig^2 * exp(-z)    -> pdf = S2/W
    float W_[4]  = {0, 0, 0, 0};
    float S1_[4] = {0, 0, 0, 0};
    float S2_[4] = {0, 0, 0, 0};
#pragma unroll
    for (int k = 0; k < KK; k++) {
        float4 pv = pi4[kb + k * CL4];
        float4 mv = mu4[kb + k * CL4];
        float4 sv = s4 [kb + k * CL4];
        float pi_l[4] = {pv.x, pv.y, pv.z, pv.w};
        float mu_l[4] = {mv.x, mv.y, mv.z, mv.w};
        float s_l[4]  = {sv.x, sv.y, sv.z, sv.w};
#pragma unroll
        for (int l = 0; l < 4; l++) {
            float w   = __expf(pi_l[l]);
            float es  = __expf(-s_l[l]);
            float z   = (x_[l] - mu_l[l]) * es;
            float ez  = __expf(-z);
            float sig = frcp(1.0f + ez);
            W_[l]  += w;
            S1_[l] = fmaf(w, sig, S1_[l]);
            S2_[l] = fmaf(w * es, sig * sig * ez, S2_[l]);
        }
    }

    const float a_l[4] = {av.x, av.y, av.z, av.w};
    const float b_l[4] = {bv.x, bv.y, bv.z, bv.w};

    float o_[4];
    float ldj = 0.0f;
#pragma unroll
    for (int l = 0; l < 4; l++) {
        float rW  = frcp(W_[l]);
        float u   = S1_[l] * rW;
        float omu = (W_[l] - S1_[l]) * rW;   // 1-u without cancellation
        u   = fminf(fmaxf(u,   1e-7f), 1.0f - 1e-7f);
        omu = fminf(fmaxf(omu, 1e-7f), 1.0f - 1e-7f);
        float logu   = __logf(u);
        float logomu = __logf(omu);
        float y       = logu - logomu;       // logit(u)
        float sldj_el = -logu - logomu;      // scale_ldj
        float logpdf  = __logf(S2_[l] * rW);
        // scale = sigmoid(a + 2) + (1 - sigmoid(2))
        float siga  = frcp(1.0f + __expf(-(a_l[l] + 2.0f)));
        float scale = siga + 0.11920292202211755f;
        o_[l] = (y + b_l[l]) * scale;
        ldj  += logpdf + sldj_el + __logf(scale);
    }
    out4[xi] = make_float4(o_[0], o_[1], o_[2], o_[3]);

    // ---- deterministic block reduction of ldj -> g_partials[blk] ----
    __shared__ float sred[TPB / 32];
    __shared__ int   s_last;
#pragma unroll
    for (int off = 16; off; off >>= 1)
        ldj += __shfl_down_sync(0xffffffffu, ldj, off);
    const int wid = threadIdx.x >> 5, lid = threadIdx.x & 31;
    if (lid == 0) sred[wid] = ldj;
    __syncthreads();
    if (threadIdx.x == 0) {
        float v = 0.0f;
#pragma unroll
        for (int w = 0; w < TPB / 32; w++) v += sred[w];
        g_partials[blk] = v;
        __threadfence();
        unsigned int old = atomicAdd(&g_counter, 1u);
        s_last = (old == NBLK - 1);
    }
    __syncthreads();

    // ---- last block performs the final deterministic reduction ----
    if (s_last) {
        // 8 warps, warp w reduces batches w and w+8 (128 partials each).
        for (int b = wid; b < BB; b += TPB / 32) {
            const float* p = g_partials + b * BLK_PER_BATCH;
            float v = p[lid] + p[lid + 32] + p[lid + 64] + p[lid + 96];
#pragma unroll
            for (int off = 16; off; off >>= 1)
                v += __shfl_down_sync(0xffffffffu, v, off);
            if (lid == 0) out_sldj[b] = sldj_in[b] + v;
        }
        if (threadIdx.x == 0) g_counter = 0;   // reset for next graph replay
    }
}

extern "C" void kernel_launch(void* const* d_in, const int* in_sizes, int n_in,
                              void* d_out, int out_size)
{
    const float4* x4  = (const float4*)d_in[0];  // x_change [B,C,L]
    const float4* a4  = (const float4*)d_in[1];  // a        [B,C,L]
    const float4* b4  = (const float4*)d_in[2];  // b        [B,C,L]
    const float4* pi4 = (const float4*)d_in[3];  // pi       [B,K,C,L]
    const float4* mu4 = (const float4*)d_in[4];  // mu       [B,K,C,L]
    const float4* s4  = (const float4*)d_in[5];  // s        [B,K,C,L]
    const float*  sldj = (const float*)d_in[6];  // sldj     [B]

    float* out = (float*)d_out;                  // [B*C*L] out, then [B] sldj_out

    coupling_fused<<<NBLK, TPB>>>(x4, a4, b4, pi4, mu4, s4, sldj,
                                  (float4*)out, out + (size_t)BB * CL);
}

// round 6
// speedup vs baseline: 1.1361x; 1.1361x over previous
#include <cuda_runtime.h>
#include <cuda_pipeline.h>

// Problem constants
#define BB 16
#define KK 8
#define CC 64
#define LL 2048
#define CL (CC*LL)                 // 131072 elements per batch
#define CL4 (CL/4)                 // 32768 float4 per batch
#define TPB 256
#define BLK_PER_BATCH (CL4/TPB)    // 128 blocks per batch
#define NBLK (BB*BLK_PER_BATCH)    // 2048 blocks total
#define STAGES 3                   // cp.async pipeline depth (12KB/stage)

// Scratch for deterministic sldj reduction (allocations are forbidden).
__device__ float        g_partials[NBLK];
__device__ unsigned int g_counter = 0;

__device__ __forceinline__ float frcp(float x) {
    float r; asm("rcp.approx.f32 %0, %1;" : "=f"(r) : "f"(x)); return r;
}

// 5 CTAs/SM: regs<=51 (compute-only needs ~40 since cp.async holds no regs),
// smem 36KB*5=180KB <= 228KB. 40/64 warps resident.
__global__ __launch_bounds__(TPB, 5) void coupling_fused(
    const float4* __restrict__ x4, const float4* __restrict__ a4,
    const float4* __restrict__ b4, const float4* __restrict__ pi4,
    const float4* __restrict__ mu4, const float4* __restrict__ s4,
    const float*  __restrict__ sldj_in,
    float4* __restrict__ out4, float* __restrict__ out_sldj)
{
    // [arr][stage][thread]: arr 0=pi, 1=mu, 2=s.  3*3*256*16B = 36KB.
    __shared__ __align__(16) float4 stg[3][STAGES][TPB];
    __shared__ float sred[TPB / 32];
    __shared__ int   s_last;

    const int tid = threadIdx.x;
    const int blk = blockIdx.x;
    const int bat = blk / BLK_PER_BATCH;
    const int j4  = (blk - bat * BLK_PER_BATCH) * TPB + tid;  // float4 idx in batch
    const int xi  = bat * CL4 + j4;              // float4 idx into [B,C,L]
    const int kb  = bat * KK * CL4 + j4;         // float4 idx into [B,K,C,L] (k=0)

    // Register loads for the per-element tensors (3 LDG.128, front-batched).
    float4 xv = x4[xi];
    float4 av = a4[xi];
    float4 bv = b4[xi];
    const float x_[4] = {xv.x, xv.y, xv.z, xv.w};

    // ---- cp.async pipeline prologue: prefetch stages 0..STAGES-1 ----
#pragma unroll
    for (int st = 0; st < STAGES; st++) {
        __pipeline_memcpy_async(&stg[0][st][tid], &pi4[kb + st * CL4], 16);
        __pipeline_memcpy_async(&stg[1][st][tid], &mu4[kb + st * CL4], 16);
        __pipeline_memcpy_async(&stg[2][st][tid], &s4 [kb + st * CL4], 16);
        __pipeline_commit();
    }

    // Single fused pass. No softmax max-subtraction: pi ~ N(0,1), exp(pi) is
    // always finite in fp32.
    //   w_k = exp(pi_k); z_k = (x - mu_k)*exp(-s_k); sig = 1/(1+exp(-z))
    //   W = sum w; S1 = sum w*sig (-> u); S2 = sum w*e^-s*sig^2*e^-z (-> pdf)
    float W_[4]  = {0, 0, 0, 0};
    float S1_[4] = {0, 0, 0, 0};
    float S2_[4] = {0, 0, 0, 0};
#pragma unroll
    for (int k = 0; k < KK; k++) {
        // Commits so far = STAGES + k; leaving STAGES-1 pending => group k done.
        __pipeline_wait_prior(STAGES - 1);
        const int st = k % STAGES;
        float4 pv = stg[0][st][tid];
        float4 mv = stg[1][st][tid];
        float4 sv = stg[2][st][tid];
        // Refill this slot for iteration k+STAGES (reads above are issued first).
        if (k + STAGES < KK) {
            __pipeline_memcpy_async(&stg[0][st][tid], &pi4[kb + (k + STAGES) * CL4], 16);
            __pipeline_memcpy_async(&stg[1][st][tid], &mu4[kb + (k + STAGES) * CL4], 16);
            __pipeline_memcpy_async(&stg[2][st][tid], &s4 [kb + (k + STAGES) * CL4], 16);
        }
        __pipeline_commit();   // one group per iteration keeps wait accounting fixed

        float pi_l[4] = {pv.x, pv.y, pv.z, pv.w};
        float mu_l[4] = {mv.x, mv.y, mv.z, mv.w};
        float s_l[4]  = {sv.x, sv.y, sv.z, sv.w};
#pragma unroll
        for (int l = 0; l < 4; l++) {
            float w   = __expf(pi_l[l]);
            float es  = __expf(-s_l[l]);
            float z   = (x_[l] - mu_l[l]) * es;
            float ez  = __expf(-z);
            float sig = frcp(1.0f + ez);
            W_[l]  += w;
            S1_[l] = fmaf(w, sig, S1_[l]);
            S2_[l] = fmaf(w * es, sig * sig * ez, S2_[l]);
        }
    }

    const float a_l[4] = {av.x, av.y, av.z, av.w};
    const float b_l[4] = {bv.x, bv.y, bv.z, bv.w};

    float o_[4];
    float ldj = 0.0f;
#pragma unroll
    for (int l = 0; l < 4; l++) {
        float rW  = frcp(W_[l]);
        float u   = S1_[l] * rW;
        float omu = (W_[l] - S1_[l]) * rW;   // 1-u without cancellation
        u   = fminf(fmaxf(u,   1e-7f), 1.0f - 1e-7f);
        omu = fminf(fmaxf(omu, 1e-7f), 1.0f - 1e-7f);
        float logu   = __logf(u);
        float logomu = __logf(omu);
        float y       = logu - logomu;       // logit(u)
        float sldj_el = -logu - logomu;      // scale_ldj
        float logpdf  = __logf(S2_[l] * rW);
        // scale = sigmoid(a + 2) + (1 - sigmoid(2))
        float siga  = frcp(1.0f + __expf(-(a_l[l] + 2.0f)));
        float scale = siga + 0.11920292202211755f;
        o_[l] = (y + b_l[l]) * scale;
        ldj  += logpdf + sldj_el + __logf(scale);
    }
    out4[xi] = make_float4(o_[0], o_[1], o_[2], o_[3]);

    // ---- deterministic block reduction of ldj -> g_partials[blk] ----
#pragma unroll
    for (int off = 16; off; off >>= 1)
        ldj += __shfl_down_sync(0xffffffffu, ldj, off);
    const int wid = tid >> 5, lid = tid & 31;
    if (lid == 0) sred[wid] = ldj;
    __syncthreads();
    if (tid == 0) {
        float v = 0.0f;
#pragma unroll
        for (int w = 0; w < TPB / 32; w++) v += sred[w];
        g_partials[blk] = v;
        __threadfence();
        unsigned int old = atomicAdd(&g_counter, 1u);
        s_last = (old == NBLK - 1);
    }
    __syncthreads();

    // ---- last block performs the final deterministic reduction ----
    if (s_last) {
        // 8 warps, warp w reduces batches w and w+8 (128 partials each).
        for (int b = wid; b < BB; b += TPB / 32) {
            const float* p = g_partials + b * BLK_PER_BATCH;
            float v = p[lid] + p[lid + 32] + p[lid + 64] + p[lid + 96];
#pragma unroll
            for (int off = 16; off; off >>= 1)
                v += __shfl_down_sync(0xffffffffu, v, off);
            if (lid == 0) out_sldj[b] = sldj_in[b] + v;
        }
        if (tid == 0) g_counter = 0;   // reset for next graph replay
    }
}

extern "C" void kernel_launch(void* const* d_in, const int* in_sizes, int n_in,
                              void* d_out, int out_size)
{
    const float4* x4  = (const float4*)d_in[0];  // x_change [B,C,L]
    const float4* a4  = (const float4*)d_in[1];  // a        [B,C,L]
    const float4* b4  = (const float4*)d_in[2];  // b        [B,C,L]
    const float4* pi4 = (const float4*)d_in[3];  // pi       [B,K,C,L]
    const float4* mu4 = (const float4*)d_in[4];  // mu       [B,K,C,L]
    const float4* s4  = (const float4*)d_in[5];  // s        [B,K,C,L]
    const float*  sldj = (const float*)d_in[6];  // sldj     [B]

    float* out = (float*)d_out;                  // [B*C*L] out, then [B] sldj_out

    coupling_fused<<<NBLK, TPB>>>(x4, a4, b4, pi4, mu4, s4, sldj,
                                  (float4*)out, out + (size_t)BB * CL);
}